// round 1
// baseline (speedup 1.0000x reference)
#include <cuda_runtime.h>
#include <math_constants.h>
#include <cstdint>

#define BB 4
#define SS 2048
#define DD 1024
#define HH 16
#define DKK 64
#define BS_ROWS (BB*SS)   // 8192

// Persistent scratch (allocation-free rule: __device__ globals)
__device__ float g_Q[(size_t)BS_ROWS * DD];
__device__ float g_K[(size_t)BS_ROWS * DD];
__device__ float g_V[(size_t)BS_ROWS * DD];
__device__ float g_A[(size_t)BS_ROWS * DD];

// ---------------------------------------------------------------------------
// SGEMM-NT: C[M,N] = A[M,K] * Bw[N,K]^T   (both operands K-contiguous)
// BM=BN=128, BK=8, 256 threads, 8x8 microtile per thread.
// ---------------------------------------------------------------------------
__global__ __launch_bounds__(256, 2)
void sgemm_nt(const float* __restrict__ A, const float* __restrict__ Bw,
              float* __restrict__ C, int M, int N, int K)
{
    __shared__ float As[8][128];
    __shared__ float Bs[8][128];

    const int t  = threadIdx.x;
    const int tx = t & 15;
    const int ty = t >> 4;
    const int rowBase = blockIdx.y * 128;
    const int colBase = blockIdx.x * 128;

    const int lr = t >> 1;          // 0..127
    const int lk = (t & 1) << 2;    // 0 or 4

    const float* Ap = A  + (size_t)(rowBase + lr) * K + lk;
    const float* Bp = Bw + (size_t)(colBase + lr) * K + lk;

    float acc[8][8];
#pragma unroll
    for (int i = 0; i < 8; ++i)
#pragma unroll
        for (int j = 0; j < 8; ++j) acc[i][j] = 0.f;

    for (int k0 = 0; k0 < K; k0 += 8) {
        float4 av = *(const float4*)(Ap + k0);
        float4 bv = *(const float4*)(Bp + k0);
        __syncthreads();
        As[lk + 0][lr] = av.x; As[lk + 1][lr] = av.y;
        As[lk + 2][lr] = av.z; As[lk + 3][lr] = av.w;
        Bs[lk + 0][lr] = bv.x; Bs[lk + 1][lr] = bv.y;
        Bs[lk + 2][lr] = bv.z; Bs[lk + 3][lr] = bv.w;
        __syncthreads();

#pragma unroll
        for (int kk = 0; kk < 8; ++kk) {
            float4 a0 = *(const float4*)&As[kk][(ty << 3) + 0];
            float4 a1 = *(const float4*)&As[kk][(ty << 3) + 4];
            float4 b0 = *(const float4*)&Bs[kk][(tx << 3) + 0];
            float4 b1 = *(const float4*)&Bs[kk][(tx << 3) + 4];
            float ar[8] = {a0.x, a0.y, a0.z, a0.w, a1.x, a1.y, a1.z, a1.w};
            float br[8] = {b0.x, b0.y, b0.z, b0.w, b1.x, b1.y, b1.z, b1.w};
#pragma unroll
            for (int i = 0; i < 8; ++i)
#pragma unroll
                for (int j = 0; j < 8; ++j)
                    acc[i][j] = fmaf(ar[i], br[j], acc[i][j]);
        }
    }

#pragma unroll
    for (int i = 0; i < 8; ++i) {
        float* Cr = C + (size_t)(rowBase + (ty << 3) + i) * N + colBase + (tx << 3);
        *(float4*)(Cr + 0) = make_float4(acc[i][0], acc[i][1], acc[i][2], acc[i][3]);
        *(float4*)(Cr + 4) = make_float4(acc[i][4], acc[i][5], acc[i][6], acc[i][7]);
    }
}

// ---------------------------------------------------------------------------
// RoPE (in place). Pair index p within a D=1024 row: head = p/32, j = p%32,
// even element offset = 2*p (heads are contiguous 64-wide blocks).
// ---------------------------------------------------------------------------
__global__ void rope_kernel(float* __restrict__ q, const int* __restrict__ pos)
{
    int i = blockIdx.x * blockDim.x + threadIdx.x;     // [0, BS_ROWS*512)
    if (i >= BS_ROWS * 512) return;
    int row = i >> 9;           // b*S + s
    int p   = i & 511;          // pair within row
    int j   = p & 31;           // pair within head
    int s   = row & (SS - 1);   // S = 2048 power of two
    float posv = (float)pos[s];
    // theta^{-j/32} = exp(-j * ln(10000)/32)
    float inv = expf(-(float)j * 0.28782313662425572f);
    float ang = posv * inv;
    float sn, cs;
    sincosf(ang, &sn, &cs);
    size_t base = (size_t)row * DD + (size_t)(p << 1);
    float x1 = q[base + 0];
    float x2 = q[base + 1];
    q[base + 0] = x1 * cs - x2 * sn;
    q[base + 1] = x1 * sn + x2 * cs;
}

// ---------------------------------------------------------------------------
// Flash attention (causal, fp32). Br=64, Bc=32. 256 threads = 8 warps.
// Warp w owns query rows [w*8, w*8+8). Lane owns key-col = lane in the score
// tile, and output dims {lane, lane+32}.
// ---------------------------------------------------------------------------
__global__ __launch_bounds__(256, 1)
void flash_kernel(const float* __restrict__ Q, const float* __restrict__ K,
                  const float* __restrict__ V, float* __restrict__ O)
{
    __shared__ float Qs[64][64];     // 16384 B
    __shared__ float Ks[32][68];     //  8704 B (pad 68: float4 rows, conflict-free)
    __shared__ float Vs[32][68];     //  8704 B
    __shared__ float Ps[64][36];     //  9216 B (pad 36: float4-aligned rows)

    const int t    = threadIdx.x;
    const int warp = t >> 5;
    const int lane = t & 31;
    const int qt = blockIdx.x;
    const int h  = blockIdx.y;
    const int b  = blockIdx.z;
    const int qbase = qt * 64;

    const float* Qg = Q + (size_t)b * SS * DD + (size_t)h * DKK;
    const float* Kg = K + (size_t)b * SS * DD + (size_t)h * DKK;
    const float* Vg = V + (size_t)b * SS * DD + (size_t)h * DKK;
    float*       Og = O + (size_t)b * SS * DD + (size_t)h * DKK;

    // Load Q tile (64x64) with float4
    for (int i = t; i < 64 * 16; i += 256) {
        int r  = i >> 4;
        int c4 = i & 15;
        *(float4*)&Qs[r][c4 << 2] =
            *(const float4*)(Qg + (size_t)(qbase + r) * DD + (c4 << 2));
    }

    float m_i[8], l_i[8], o0[8], o1[8];
#pragma unroll
    for (int rr = 0; rr < 8; ++rr) {
        m_i[rr] = -CUDART_INF_F; l_i[rr] = 0.f; o0[rr] = 0.f; o1[rr] = 0.f;
    }

    const int ktmax = 2 * qt + 1;   // last key tile index touching this q tile
    for (int kt = 0; kt <= ktmax; ++kt) {
        const int kbase = kt << 5;
        __syncthreads();
        // Load K,V tiles (32x64), coalesced
        for (int i = t; i < 32 * 64; i += 256) {
            int r = i >> 6, c = i & 63;
            Ks[r][c] = Kg[(size_t)(kbase + r) * DD + c];
            Vs[r][c] = Vg[(size_t)(kbase + r) * DD + c];
        }
        __syncthreads();

        // Scores + online softmax (warp handles its 8 rows; lane = key col)
#pragma unroll
        for (int rr = 0; rr < 8; ++rr) {
            const int r = (warp << 3) + rr;
            float s = 0.f;
#pragma unroll
            for (int d4 = 0; d4 < 16; ++d4) {
                float4 qv = *(const float4*)&Qs[r][d4 << 2];
                float4 kv = *(const float4*)&Ks[lane][d4 << 2];
                s = fmaf(qv.x, kv.x, s);
                s = fmaf(qv.y, kv.y, s);
                s = fmaf(qv.z, kv.z, s);
                s = fmaf(qv.w, kv.w, s);
            }
            s *= 0.125f;  // 1/sqrt(64)
            if (kbase + lane > qbase + r) s = -CUDART_INF_F;  // causal

            float mt = s;
#pragma unroll
            for (int off = 16; off > 0; off >>= 1)
                mt = fmaxf(mt, __shfl_xor_sync(0xffffffffu, mt, off));
            float mnew = fmaxf(m_i[rr], mt);
            float p    = __expf(s - mnew);
            float corr = __expf(m_i[rr] - mnew);
            float ps = p;
#pragma unroll
            for (int off = 16; off > 0; off >>= 1)
                ps += __shfl_xor_sync(0xffffffffu, ps, off);
            l_i[rr] = l_i[rr] * corr + ps;
            m_i[rr] = mnew;
            o0[rr] *= corr;
            o1[rr] *= corr;
            Ps[r][lane] = p;
        }
        __syncwarp();

        // O += P @ V  (lane owns dims lane, lane+32)
#pragma unroll
        for (int rr = 0; rr < 8; ++rr) {
            const int r = (warp << 3) + rr;
            float a0 = 0.f, a1 = 0.f;
#pragma unroll
            for (int c4 = 0; c4 < 8; ++c4) {
                float4 pv = *(const float4*)&Ps[r][c4 << 2];
                const int c = c4 << 2;
                a0 = fmaf(pv.x, Vs[c + 0][lane], a0);
                a0 = fmaf(pv.y, Vs[c + 1][lane], a0);
                a0 = fmaf(pv.z, Vs[c + 2][lane], a0);
                a0 = fmaf(pv.w, Vs[c + 3][lane], a0);
                a1 = fmaf(pv.x, Vs[c + 0][lane + 32], a1);
                a1 = fmaf(pv.y, Vs[c + 1][lane + 32], a1);
                a1 = fmaf(pv.z, Vs[c + 2][lane + 32], a1);
                a1 = fmaf(pv.w, Vs[c + 3][lane + 32], a1);
            }
            o0[rr] += a0;
            o1[rr] += a1;
        }
    }

    // Epilogue
#pragma unroll
    for (int rr = 0; rr < 8; ++rr) {
        const int r = (warp << 3) + rr;
        float inv = 1.f / l_i[rr];
        Og[(size_t)(qbase + r) * DD + lane]      = o0[rr] * inv;
        Og[(size_t)(qbase + r) * DD + lane + 32] = o1[rr] * inv;
    }
}

// ---------------------------------------------------------------------------
extern "C" void kernel_launch(void* const* d_in, const int* in_sizes, int n_in,
                              void* d_out, int out_size)
{
    const float* x   = (const float*)d_in[0];
    const int*   pos = (const int*)  d_in[1];
    const float* Wq  = (const float*)d_in[2];
    const float* Wk  = (const float*)d_in[3];
    const float* Wv  = (const float*)d_in[4];
    const float* Wo  = (const float*)d_in[5];
    float* out = (float*)d_out;

    float *Q, *K, *V, *Aw;
    cudaGetSymbolAddress((void**)&Q,  g_Q);
    cudaGetSymbolAddress((void**)&K,  g_K);
    cudaGetSymbolAddress((void**)&V,  g_V);
    cudaGetSymbolAddress((void**)&Aw, g_A);

    dim3 gg(DD / 128, BS_ROWS / 128);       // (8, 64)

    sgemm_nt<<<gg, 256>>>(x, Wq, Q, BS_ROWS, DD, DD);
    sgemm_nt<<<gg, 256>>>(x, Wk, K, BS_ROWS, DD, DD);
    sgemm_nt<<<gg, 256>>>(x, Wv, V, BS_ROWS, DD, DD);

    const int rope_elems = BS_ROWS * 512;
    rope_kernel<<<rope_elems / 256, 256>>>(Q, pos);
    rope_kernel<<<rope_elems / 256, 256>>>(K, pos);

    flash_kernel<<<dim3(SS / 64, HH, BB), 256>>>(Q, K, V, Aw);

    sgemm_nt<<<gg, 256>>>(Aw, Wo, out, BS_ROWS, DD, DD);
}

// round 3
// speedup vs baseline: 1.4726x; 1.4726x over previous
#include <cuda_runtime.h>
#include <math_constants.h>
#include <cstdint>

#define BB 4
#define SS 2048
#define DD 1024
#define HH 16
#define DKK 64
#define BS_ROWS (BB*SS)   // 8192

// Persistent scratch (allocation-free rule: __device__ globals)
__device__ float g_Q[(size_t)BS_ROWS * DD];
__device__ float g_K[(size_t)BS_ROWS * DD];
__device__ float g_V[(size_t)BS_ROWS * DD];
__device__ float g_A[(size_t)BS_ROWS * DD];

__device__ __forceinline__ uint32_t f2tf32(float x) {
    uint32_t u;
    asm("cvt.rna.tf32.f32 %0, %1;" : "=r"(u) : "f"(x));
    return u;
}

__device__ __forceinline__ void mma_tf32(float& c0, float& c1, float& c2, float& c3,
                                         uint32_t a0, uint32_t a1, uint32_t a2, uint32_t a3,
                                         uint32_t b0, uint32_t b1) {
    asm volatile(
        "mma.sync.aligned.m16n8k8.row.col.f32.tf32.tf32.f32 "
        "{%0,%1,%2,%3}, {%4,%5,%6,%7}, {%8,%9}, {%0,%1,%2,%3};"
        : "+f"(c0), "+f"(c1), "+f"(c2), "+f"(c3)
        : "r"(a0), "r"(a1), "r"(a2), "r"(a3), "r"(b0), "r"(b1));
}

// ===========================================================================
// Tensor-core GEMM-NT (tf32 mma.sync): C[M,N] = A[M,K] * Bw[N,K]^T
// BM=BN=128, BK=32, 256 threads = 8 warps (4 m-warps x 2 n-warps),
// warp tile 32x64 (2 m16-tiles x 8 n8-tiles). Smem padded [128][36].
// ===========================================================================
#define BKG 32
#define LDS_PAD 36

__global__ __launch_bounds__(256, 2)
void gemm_tf32(const float* __restrict__ A, const float* __restrict__ Bw,
               float* __restrict__ C, int M, int N, int K)
{
    __shared__ uint32_t As[128][LDS_PAD];
    __shared__ uint32_t Bs[128][LDS_PAD];

    const int t    = threadIdx.x;
    const int wid  = t >> 5;
    const int lane = t & 31;
    const int g    = lane >> 2;    // group id (row within 8)
    const int tg   = lane & 3;     // thread-in-group (col within 4)
    const int warp_m = wid & 3;    // 0..3 -> 32-row slices
    const int warp_n = wid >> 2;   // 0..1 -> 64-col slices

    const int rowBase = blockIdx.y * 128;
    const int colBase = blockIdx.x * 128;

    const float* Ag = A  + (size_t)rowBase * K;
    const float* Bg = Bw + (size_t)colBase * K;

    float acc[2][8][4];
#pragma unroll
    for (int mt = 0; mt < 2; ++mt)
#pragma unroll
        for (int nt = 0; nt < 8; ++nt)
#pragma unroll
            for (int i = 0; i < 4; ++i) acc[mt][nt][i] = 0.f;

    // loader indices: each thread moves 4 float4 per tile (128x32)
    const int lr0 = t >> 3;         // 0..31  (row stride 32 per p)
    const int lc4 = (t & 7) << 2;   // col 0,4,..,28

    for (int k0 = 0; k0 < K; k0 += BKG) {
        __syncthreads();
#pragma unroll
        for (int p = 0; p < 4; ++p) {
            int r = p * 32 + lr0;
            float4 va = *(const float4*)(Ag + (size_t)r * K + k0 + lc4);
            float4 vb = *(const float4*)(Bg + (size_t)r * K + k0 + lc4);
            As[r][lc4 + 0] = f2tf32(va.x); As[r][lc4 + 1] = f2tf32(va.y);
            As[r][lc4 + 2] = f2tf32(va.z); As[r][lc4 + 3] = f2tf32(va.w);
            Bs[r][lc4 + 0] = f2tf32(vb.x); Bs[r][lc4 + 1] = f2tf32(vb.y);
            Bs[r][lc4 + 2] = f2tf32(vb.z); Bs[r][lc4 + 3] = f2tf32(vb.w);
        }
        __syncthreads();

#pragma unroll
        for (int kk = 0; kk < 4; ++kk) {
            const int ks = kk << 3;
            uint32_t afr[2][4];
#pragma unroll
            for (int mt = 0; mt < 2; ++mt) {
                const int ar = warp_m * 32 + mt * 16 + g;
                afr[mt][0] = As[ar    ][ks + tg];
                afr[mt][1] = As[ar + 8][ks + tg];
                afr[mt][2] = As[ar    ][ks + tg + 4];
                afr[mt][3] = As[ar + 8][ks + tg + 4];
            }
#pragma unroll
            for (int nt = 0; nt < 8; ++nt) {
                const int br = warp_n * 64 + nt * 8 + g;
                uint32_t b0 = Bs[br][ks + tg];
                uint32_t b1 = Bs[br][ks + tg + 4];
#pragma unroll
                for (int mt = 0; mt < 2; ++mt)
                    mma_tf32(acc[mt][nt][0], acc[mt][nt][1],
                             acc[mt][nt][2], acc[mt][nt][3],
                             afr[mt][0], afr[mt][1], afr[mt][2], afr[mt][3],
                             b0, b1);
            }
        }
    }

    // Epilogue: direct float2 stores
#pragma unroll
    for (int mt = 0; mt < 2; ++mt) {
        const int r0 = rowBase + warp_m * 32 + mt * 16 + g;
#pragma unroll
        for (int nt = 0; nt < 8; ++nt) {
            const int c = colBase + warp_n * 64 + nt * 8 + tg * 2;
            *(float2*)(C + (size_t)r0 * N + c) =
                make_float2(acc[mt][nt][0], acc[mt][nt][1]);
            *(float2*)(C + (size_t)(r0 + 8) * N + c) =
                make_float2(acc[mt][nt][2], acc[mt][nt][3]);
        }
    }
}

// ---------------------------------------------------------------------------
// RoPE (in place).
// ---------------------------------------------------------------------------
__global__ void rope_kernel(float* __restrict__ q, const int* __restrict__ pos)
{
    int i = blockIdx.x * blockDim.x + threadIdx.x;
    if (i >= BS_ROWS * 512) return;
    int row = i >> 9;
    int p   = i & 511;
    int j   = p & 31;
    int s   = row & (SS - 1);
    float posv = (float)pos[s];
    float inv = expf(-(float)j * 0.28782313662425572f);
    float ang = posv * inv;
    float sn, cs;
    sincosf(ang, &sn, &cs);
    size_t base = (size_t)row * DD + (size_t)(p << 1);
    float x1 = q[base + 0];
    float x2 = q[base + 1];
    q[base + 0] = x1 * cs - x2 * sn;
    q[base + 1] = x1 * sn + x2 * cs;
}

// ---------------------------------------------------------------------------
// Flash attention (causal, fp32 SIMT). Br=64, Bc=32, 256 threads.
// ---------------------------------------------------------------------------
__global__ __launch_bounds__(256, 1)
void flash_kernel(const float* __restrict__ Q, const float* __restrict__ K,
                  const float* __restrict__ V, float* __restrict__ O)
{
    __shared__ float Qs[64][64];
    __shared__ float Ks[32][68];
    __shared__ float Vs[32][68];
    __shared__ float Ps[64][36];

    const int t    = threadIdx.x;
    const int warp = t >> 5;
    const int lane = t & 31;
    const int qt = blockIdx.x;
    const int h  = blockIdx.y;
    const int b  = blockIdx.z;
    const int qbase = qt * 64;

    const float* Qg = Q + (size_t)b * SS * DD + (size_t)h * DKK;
    const float* Kg = K + (size_t)b * SS * DD + (size_t)h * DKK;
    const float* Vg = V + (size_t)b * SS * DD + (size_t)h * DKK;
    float*       Og = O + (size_t)b * SS * DD + (size_t)h * DKK;

    for (int i = t; i < 64 * 16; i += 256) {
        int r  = i >> 4;
        int c4 = i & 15;
        *(float4*)&Qs[r][c4 << 2] =
            *(const float4*)(Qg + (size_t)(qbase + r) * DD + (c4 << 2));
    }

    float m_i[8], l_i[8], o0[8], o1[8];
#pragma unroll
    for (int rr = 0; rr < 8; ++rr) {
        m_i[rr] = -CUDART_INF_F; l_i[rr] = 0.f; o0[rr] = 0.f; o1[rr] = 0.f;
    }

    const int ktmax = 2 * qt + 1;
    for (int kt = 0; kt <= ktmax; ++kt) {
        const int kbase = kt << 5;
        __syncthreads();
        for (int i = t; i < 32 * 64; i += 256) {
            int r = i >> 6, c = i & 63;
            Ks[r][c] = Kg[(size_t)(kbase + r) * DD + c];
            Vs[r][c] = Vg[(size_t)(kbase + r) * DD + c];
        }
        __syncthreads();

#pragma unroll
        for (int rr = 0; rr < 8; ++rr) {
            const int r = (warp << 3) + rr;
            float s = 0.f;
#pragma unroll
            for (int d4 = 0; d4 < 16; ++d4) {
                float4 qv = *(const float4*)&Qs[r][d4 << 2];
                float4 kv = *(const float4*)&Ks[lane][d4 << 2];
                s = fmaf(qv.x, kv.x, s);
                s = fmaf(qv.y, kv.y, s);
                s = fmaf(qv.z, kv.z, s);
                s = fmaf(qv.w, kv.w, s);
            }
            s *= 0.125f;
            if (kbase + lane > qbase + r) s = -CUDART_INF_F;

            float mt = s;
#pragma unroll
            for (int off = 16; off > 0; off >>= 1)
                mt = fmaxf(mt, __shfl_xor_sync(0xffffffffu, mt, off));
            float mnew = fmaxf(m_i[rr], mt);
            float p    = __expf(s - mnew);
            float corr = __expf(m_i[rr] - mnew);
            float ps = p;
#pragma unroll
            for (int off = 16; off > 0; off >>= 1)
                ps += __shfl_xor_sync(0xffffffffu, ps, off);
            l_i[rr] = l_i[rr] * corr + ps;
            m_i[rr] = mnew;
            o0[rr] *= corr;
            o1[rr] *= corr;
            Ps[r][lane] = p;
        }
        __syncwarp();

#pragma unroll
        for (int rr = 0; rr < 8; ++rr) {
            const int r = (warp << 3) + rr;
            float a0 = 0.f, a1 = 0.f;
#pragma unroll
            for (int c4 = 0; c4 < 8; ++c4) {
                float4 pv = *(const float4*)&Ps[r][c4 << 2];
                const int c = c4 << 2;
                a0 = fmaf(pv.x, Vs[c + 0][lane], a0);
                a0 = fmaf(pv.y, Vs[c + 1][lane], a0);
                a0 = fmaf(pv.z, Vs[c + 2][lane], a0);
                a0 = fmaf(pv.w, Vs[c + 3][lane], a0);
                a1 = fmaf(pv.x, Vs[c + 0][lane + 32], a1);
                a1 = fmaf(pv.y, Vs[c + 1][lane + 32], a1);
                a1 = fmaf(pv.z, Vs[c + 2][lane + 32], a1);
                a1 = fmaf(pv.w, Vs[c + 3][lane + 32], a1);
            }
            o0[rr] += a0;
            o1[rr] += a1;
        }
    }

#pragma unroll
    for (int rr = 0; rr < 8; ++rr) {
        const int r = (warp << 3) + rr;
        float inv = 1.f / l_i[rr];
        Og[(size_t)(qbase + r) * DD + lane]      = o0[rr] * inv;
        Og[(size_t)(qbase + r) * DD + lane + 32] = o1[rr] * inv;
    }
}

// ---------------------------------------------------------------------------
extern "C" void kernel_launch(void* const* d_in, const int* in_sizes, int n_in,
                              void* d_out, int out_size)
{
    const float* x   = (const float*)d_in[0];
    const int*   pos = (const int*)  d_in[1];
    const float* Wq  = (const float*)d_in[2];
    const float* Wk  = (const float*)d_in[3];
    const float* Wv  = (const float*)d_in[4];
    const float* Wo  = (const float*)d_in[5];
    float* out = (float*)d_out;

    float *Q, *K, *V, *Aw;
    cudaGetSymbolAddress((void**)&Q,  g_Q);
    cudaGetSymbolAddress((void**)&K,  g_K);
    cudaGetSymbolAddress((void**)&V,  g_V);
    cudaGetSymbolAddress((void**)&Aw, g_A);

    dim3 gg(DD / 128, BS_ROWS / 128);   // (8, 64)

    gemm_tf32<<<gg, 256>>>(x, Wq, Q, BS_ROWS, DD, DD);
    gemm_tf32<<<gg, 256>>>(x, Wk, K, BS_ROWS, DD, DD);
    gemm_tf32<<<gg, 256>>>(x, Wv, V, BS_ROWS, DD, DD);

    const int rope_elems = BS_ROWS * 512;
    rope_kernel<<<rope_elems / 256, 256>>>(Q, pos);
    rope_kernel<<<rope_elems / 256, 256>>>(K, pos);

    flash_kernel<<<dim3(SS / 64, HH, BB), 256>>>(Q, K, V, Aw);

    gemm_tf32<<<gg, 256>>>(Aw, Wo, out, BS_ROWS, DD, DD);
}

// round 6
// speedup vs baseline: 3.0100x; 2.0439x over previous
#include <cuda_runtime.h>
#include <math_constants.h>
#include <cstdint>

#define BB 4
#define SS 2048
#define DD 1024
#define HH 16
#define DKK 64
#define BS_ROWS (BB*SS)   // 8192

// Persistent scratch (allocation-free rule: __device__ globals)
__device__ float g_Q[(size_t)BS_ROWS * DD];
__device__ float g_K[(size_t)BS_ROWS * DD];
__device__ float g_V[(size_t)BS_ROWS * DD];
__device__ float g_A[(size_t)BS_ROWS * DD];

__device__ __forceinline__ uint32_t f2tf32(float x) {
    uint32_t u;
    asm("cvt.rna.tf32.f32 %0, %1;" : "=r"(u) : "f"(x));
    return u;
}

__device__ __forceinline__ float ex2f(float x) {
    float y;
    asm("ex2.approx.f32 %0, %1;" : "=f"(y) : "f"(x));
    return y;
}

__device__ __forceinline__ void mma_tf32(float& c0, float& c1, float& c2, float& c3,
                                         uint32_t a0, uint32_t a1, uint32_t a2, uint32_t a3,
                                         uint32_t b0, uint32_t b1) {
    asm volatile(
        "mma.sync.aligned.m16n8k8.row.col.f32.tf32.tf32.f32 "
        "{%0,%1,%2,%3}, {%4,%5,%6,%7}, {%8,%9}, {%0,%1,%2,%3};"
        : "+f"(c0), "+f"(c1), "+f"(c2), "+f"(c3)
        : "r"(a0), "r"(a1), "r"(a2), "r"(a3), "r"(b0), "r"(b1));
}

// ===========================================================================
// Tensor-core GEMM-NT (tf32 mma.sync): C[M,N] = A[M,K] * Bw[N,K]^T
// ===========================================================================
#define BKG 32
#define LDS_PAD 36

__global__ __launch_bounds__(256, 2)
void gemm_tf32(const float* __restrict__ A, const float* __restrict__ Bw,
               float* __restrict__ C, int M, int N, int K)
{
    __shared__ uint32_t As[128][LDS_PAD];
    __shared__ uint32_t Bs[128][LDS_PAD];

    const int t    = threadIdx.x;
    const int wid  = t >> 5;
    const int lane = t & 31;
    const int g    = lane >> 2;
    const int tg   = lane & 3;
    const int warp_m = wid & 3;
    const int warp_n = wid >> 2;

    const int rowBase = blockIdx.y * 128;
    const int colBase = blockIdx.x * 128;

    const float* Ag = A  + (size_t)rowBase * K;
    const float* Bg = Bw + (size_t)colBase * K;

    float acc[2][8][4];
#pragma unroll
    for (int mt = 0; mt < 2; ++mt)
#pragma unroll
        for (int nt = 0; nt < 8; ++nt)
#pragma unroll
            for (int i = 0; i < 4; ++i) acc[mt][nt][i] = 0.f;

    const int lr0 = t >> 3;
    const int lc4 = (t & 7) << 2;

    for (int k0 = 0; k0 < K; k0 += BKG) {
        __syncthreads();
#pragma unroll
        for (int p = 0; p < 4; ++p) {
            int r = p * 32 + lr0;
            float4 va = *(const float4*)(Ag + (size_t)r * K + k0 + lc4);
            float4 vb = *(const float4*)(Bg + (size_t)r * K + k0 + lc4);
            As[r][lc4 + 0] = f2tf32(va.x); As[r][lc4 + 1] = f2tf32(va.y);
            As[r][lc4 + 2] = f2tf32(va.z); As[r][lc4 + 3] = f2tf32(va.w);
            Bs[r][lc4 + 0] = f2tf32(vb.x); Bs[r][lc4 + 1] = f2tf32(vb.y);
            Bs[r][lc4 + 2] = f2tf32(vb.z); Bs[r][lc4 + 3] = f2tf32(vb.w);
        }
        __syncthreads();

#pragma unroll
        for (int kk = 0; kk < 4; ++kk) {
            const int ks = kk << 3;
            uint32_t afr[2][4];
#pragma unroll
            for (int mt = 0; mt < 2; ++mt) {
                const int ar = warp_m * 32 + mt * 16 + g;
                afr[mt][0] = As[ar    ][ks + tg];
                afr[mt][1] = As[ar + 8][ks + tg];
                afr[mt][2] = As[ar    ][ks + tg + 4];
                afr[mt][3] = As[ar + 8][ks + tg + 4];
            }
#pragma unroll
            for (int nt = 0; nt < 8; ++nt) {
                const int br = warp_n * 64 + nt * 8 + g;
                uint32_t b0 = Bs[br][ks + tg];
                uint32_t b1 = Bs[br][ks + tg + 4];
#pragma unroll
                for (int mt = 0; mt < 2; ++mt)
                    mma_tf32(acc[mt][nt][0], acc[mt][nt][1],
                             acc[mt][nt][2], acc[mt][nt][3],
                             afr[mt][0], afr[mt][1], afr[mt][2], afr[mt][3],
                             b0, b1);
            }
        }
    }

#pragma unroll
    for (int mt = 0; mt < 2; ++mt) {
        const int r0 = rowBase + warp_m * 32 + mt * 16 + g;
#pragma unroll
        for (int nt = 0; nt < 8; ++nt) {
            const int c = colBase + warp_n * 64 + nt * 8 + tg * 2;
            *(float2*)(C + (size_t)r0 * N + c) =
                make_float2(acc[mt][nt][0], acc[mt][nt][1]);
            *(float2*)(C + (size_t)(r0 + 8) * N + c) =
                make_float2(acc[mt][nt][2], acc[mt][nt][3]);
        }
    }
}

// ---------------------------------------------------------------------------
// RoPE (in place).
// ---------------------------------------------------------------------------
__global__ void rope_kernel(float* __restrict__ q, const int* __restrict__ pos)
{
    int i = blockIdx.x * blockDim.x + threadIdx.x;
    if (i >= BS_ROWS * 512) return;
    int row = i >> 9;
    int p   = i & 511;
    int j   = p & 31;
    int s   = row & (SS - 1);
    float posv = (float)pos[s];
    float inv = expf(-(float)j * 0.28782313662425572f);
    float ang = posv * inv;
    float sn, cs;
    sincosf(ang, &sn, &cs);
    size_t base = (size_t)row * DD + (size_t)(p << 1);
    float x1 = q[base + 0];
    float x2 = q[base + 1];
    q[base + 0] = x1 * cs - x2 * sn;
    q[base + 1] = x1 * sn + x2 * cs;
}

// ===========================================================================
// Tensor-core flash attention (causal), 3x-tf32 error-compensated.
// Br=Bc=64, 128 threads (4 warps), warp owns 16 query rows.
// smem: KsH/KsL/VsH/VsL/PsH/PsL, each 64 x 68 u32 (padded, conflict-free).
// ===========================================================================
#define FP 68
#define F_SMEM (6 * 64 * FP * 4)   // 104448 B

__global__ __launch_bounds__(128, 2)
void flash_mma(const float* __restrict__ Q, const float* __restrict__ K,
               const float* __restrict__ V, float* __restrict__ O)
{
    extern __shared__ uint32_t fsm[];
    uint32_t* KsH = fsm;
    uint32_t* KsL = KsH + 64 * FP;
    uint32_t* VsH = KsL + 64 * FP;
    uint32_t* VsL = VsH + 64 * FP;
    uint32_t* PsH = VsL + 64 * FP;
    uint32_t* PsL = PsH + 64 * FP;

    const int t    = threadIdx.x;
    const int wid  = t >> 5;
    const int lane = t & 31;
    const int g    = lane >> 2;
    const int tg   = lane & 3;
    const int qbase = blockIdx.x * 64;

    const size_t hb = (size_t)blockIdx.z * SS * DD + (size_t)blockIdx.y * DKK;
    const float* Qg = Q + hb;
    const float* Kg = K + hb;
    const float* Vg = V + hb;
    float*       Og = O + hb;

    const float QS = 0.125f * 1.4426950408889634f;   // 1/sqrt(64) * log2(e)

    // Stage Q (scaled) hi/lo into KsH/KsL, then pull fragments to registers
#pragma unroll
    for (int p = 0; p < 8; ++p) {
        int idx = p * 128 + t;
        int r = idx >> 4, c = (idx & 15) << 2;
        float4 v = *(const float4*)(Qg + (size_t)(qbase + r) * DD + c);
        float f0 = v.x * QS, f1 = v.y * QS, f2 = v.z * QS, f3 = v.w * QS;
        uint4 h, l;
        h.x = f2tf32(f0); l.x = f2tf32(f0 - __uint_as_float(h.x));
        h.y = f2tf32(f1); l.y = f2tf32(f1 - __uint_as_float(h.y));
        h.z = f2tf32(f2); l.z = f2tf32(f2 - __uint_as_float(h.z));
        h.w = f2tf32(f3); l.w = f2tf32(f3 - __uint_as_float(h.w));
        *(uint4*)&KsH[r * FP + c] = h;
        *(uint4*)&KsL[r * FP + c] = l;
    }
    __syncthreads();

    uint32_t qh[8][4], ql[8][4];
    const int arow = wid * 16 + g;
#pragma unroll
    for (int ks = 0; ks < 8; ++ks) {
        int kc = ks * 8 + tg;
        qh[ks][0] = KsH[arow * FP + kc];
        qh[ks][1] = KsH[(arow + 8) * FP + kc];
        qh[ks][2] = KsH[arow * FP + kc + 4];
        qh[ks][3] = KsH[(arow + 8) * FP + kc + 4];
        ql[ks][0] = KsL[arow * FP + kc];
        ql[ks][1] = KsL[(arow + 8) * FP + kc];
        ql[ks][2] = KsL[arow * FP + kc + 4];
        ql[ks][3] = KsL[(arow + 8) * FP + kc + 4];
    }
    __syncthreads();

    float m0 = -CUDART_INF_F, m1 = -CUDART_INF_F, l0 = 0.f, l1 = 0.f;
    float o[8][4];
#pragma unroll
    for (int nt = 0; nt < 8; ++nt)
#pragma unroll
        for (int i = 0; i < 4; ++i) o[nt][i] = 0.f;

    for (int kt = 0; kt <= (int)blockIdx.x; ++kt) {
        const int kb = kt * 64;

        // Load K, V tiles, hi/lo split, tf32 bits
#pragma unroll
        for (int p = 0; p < 8; ++p) {
            int idx = p * 128 + t;
            int r = idx >> 4, c = (idx & 15) << 2;
            float4 kv = *(const float4*)(Kg + (size_t)(kb + r) * DD + c);
            float4 vv = *(const float4*)(Vg + (size_t)(kb + r) * DD + c);
            uint4 kh, kl, vh, vl;
            kh.x = f2tf32(kv.x); kl.x = f2tf32(kv.x - __uint_as_float(kh.x));
            kh.y = f2tf32(kv.y); kl.y = f2tf32(kv.y - __uint_as_float(kh.y));
            kh.z = f2tf32(kv.z); kl.z = f2tf32(kv.z - __uint_as_float(kh.z));
            kh.w = f2tf32(kv.w); kl.w = f2tf32(kv.w - __uint_as_float(kh.w));
            vh.x = f2tf32(vv.x); vl.x = f2tf32(vv.x - __uint_as_float(vh.x));
            vh.y = f2tf32(vv.y); vl.y = f2tf32(vv.y - __uint_as_float(vh.y));
            vh.z = f2tf32(vv.z); vl.z = f2tf32(vv.z - __uint_as_float(vh.z));
            vh.w = f2tf32(vv.w); vl.w = f2tf32(vv.w - __uint_as_float(vh.w));
            *(uint4*)&KsH[r * FP + c] = kh;
            *(uint4*)&KsL[r * FP + c] = kl;
            *(uint4*)&VsH[r * FP + c] = vh;
            *(uint4*)&VsL[r * FP + c] = vl;
        }
        __syncthreads();

        // S = (Q * scale) K^T  -- 3x tf32
        float s[8][4];
#pragma unroll
        for (int nt = 0; nt < 8; ++nt)
#pragma unroll
            for (int i = 0; i < 4; ++i) s[nt][i] = 0.f;

#pragma unroll
        for (int ks = 0; ks < 8; ++ks) {
            const int kc = ks * 8;
#pragma unroll
            for (int nt = 0; nt < 8; ++nt) {
                const int br = (nt * 8 + g) * FP + kc;
                uint32_t bh0 = KsH[br + tg], bh1 = KsH[br + tg + 4];
                uint32_t bl0 = KsL[br + tg], bl1 = KsL[br + tg + 4];
                mma_tf32(s[nt][0], s[nt][1], s[nt][2], s[nt][3],
                         qh[ks][0], qh[ks][1], qh[ks][2], qh[ks][3], bh0, bh1);
                mma_tf32(s[nt][0], s[nt][1], s[nt][2], s[nt][3],
                         ql[ks][0], ql[ks][1], ql[ks][2], ql[ks][3], bh0, bh1);
                mma_tf32(s[nt][0], s[nt][1], s[nt][2], s[nt][3],
                         qh[ks][0], qh[ks][1], qh[ks][2], qh[ks][3], bl0, bl1);
            }
        }

        // Causal mask (diagonal tile only)
        if (kt == (int)blockIdx.x) {
            const int row0 = qbase + wid * 16 + g;
#pragma unroll
            for (int nt = 0; nt < 8; ++nt) {
                const int c0 = kb + nt * 8 + 2 * tg;
                if (c0     > row0)     s[nt][0] = -CUDART_INF_F;
                if (c0 + 1 > row0)     s[nt][1] = -CUDART_INF_F;
                if (c0     > row0 + 8) s[nt][2] = -CUDART_INF_F;
                if (c0 + 1 > row0 + 8) s[nt][3] = -CUDART_INF_F;
            }
        }

        // Online softmax (exp2 domain)
        float mx0 = -CUDART_INF_F, mx1 = -CUDART_INF_F;
#pragma unroll
        for (int nt = 0; nt < 8; ++nt) {
            mx0 = fmaxf(mx0, fmaxf(s[nt][0], s[nt][1]));
            mx1 = fmaxf(mx1, fmaxf(s[nt][2], s[nt][3]));
        }
        mx0 = fmaxf(mx0, __shfl_xor_sync(0xffffffffu, mx0, 1));
        mx0 = fmaxf(mx0, __shfl_xor_sync(0xffffffffu, mx0, 2));
        mx1 = fmaxf(mx1, __shfl_xor_sync(0xffffffffu, mx1, 1));
        mx1 = fmaxf(mx1, __shfl_xor_sync(0xffffffffu, mx1, 2));

        float mn0 = fmaxf(m0, mx0), mn1 = fmaxf(m1, mx1);
        float cr0 = ex2f(m0 - mn0), cr1 = ex2f(m1 - mn1);
        float sum0 = 0.f, sum1 = 0.f;
        const int prow = (wid * 16 + g) * FP;
#pragma unroll
        for (int nt = 0; nt < 8; ++nt) {
            float p0 = ex2f(s[nt][0] - mn0), p1 = ex2f(s[nt][1] - mn0);
            float p2 = ex2f(s[nt][2] - mn1), p3 = ex2f(s[nt][3] - mn1);
            sum0 += p0 + p1;
            sum1 += p2 + p3;
            uint32_t h0 = f2tf32(p0), h1 = f2tf32(p1);
            uint32_t h2 = f2tf32(p2), h3 = f2tf32(p3);
            const int pc = nt * 8 + 2 * tg;
            *(uint2*)&PsH[prow + pc]          = make_uint2(h0, h1);
            *(uint2*)&PsH[prow + 8 * FP + pc] = make_uint2(h2, h3);
            *(uint2*)&PsL[prow + pc]          = make_uint2(
                f2tf32(p0 - __uint_as_float(h0)), f2tf32(p1 - __uint_as_float(h1)));
            *(uint2*)&PsL[prow + 8 * FP + pc] = make_uint2(
                f2tf32(p2 - __uint_as_float(h2)), f2tf32(p3 - __uint_as_float(h3)));
        }
        sum0 += __shfl_xor_sync(0xffffffffu, sum0, 1);
        sum0 += __shfl_xor_sync(0xffffffffu, sum0, 2);
        sum1 += __shfl_xor_sync(0xffffffffu, sum1, 1);
        sum1 += __shfl_xor_sync(0xffffffffu, sum1, 2);
        l0 = l0 * cr0 + sum0;
        l1 = l1 * cr1 + sum1;
        m0 = mn0; m1 = mn1;
#pragma unroll
        for (int nt = 0; nt < 8; ++nt) {
            o[nt][0] *= cr0; o[nt][1] *= cr0;
            o[nt][2] *= cr1; o[nt][3] *= cr1;
        }
        __syncwarp();

        // O += P V  -- 3x tf32
#pragma unroll
        for (int ks = 0; ks < 8; ++ks) {
            const int kc = ks * 8;
            uint32_t ah0 = PsH[prow + kc + tg];
            uint32_t ah1 = PsH[prow + 8 * FP + kc + tg];
            uint32_t ah2 = PsH[prow + kc + tg + 4];
            uint32_t ah3 = PsH[prow + 8 * FP + kc + tg + 4];
            uint32_t al0 = PsL[prow + kc + tg];
            uint32_t al1 = PsL[prow + 8 * FP + kc + tg];
            uint32_t al2 = PsL[prow + kc + tg + 4];
            uint32_t al3 = PsL[prow + 8 * FP + kc + tg + 4];
#pragma unroll
            for (int nt = 0; nt < 8; ++nt) {
                const int vb = (kc + tg) * FP + nt * 8 + g;
                uint32_t bh0 = VsH[vb], bh1 = VsH[vb + 4 * FP];
                uint32_t bl0 = VsL[vb], bl1 = VsL[vb + 4 * FP];
                mma_tf32(o[nt][0], o[nt][1], o[nt][2], o[nt][3],
                         ah0, ah1, ah2, ah3, bh0, bh1);
                mma_tf32(o[nt][0], o[nt][1], o[nt][2], o[nt][3],
                         al0, al1, al2, al3, bh0, bh1);
                mma_tf32(o[nt][0], o[nt][1], o[nt][2], o[nt][3],
                         ah0, ah1, ah2, ah3, bl0, bl1);
            }
        }
        __syncthreads();
    }

    // Epilogue
    const float i0 = 1.0f / l0, i1 = 1.0f / l1;
    const int row0 = qbase + wid * 16 + g;
#pragma unroll
    for (int nt = 0; nt < 8; ++nt) {
        const int c = nt * 8 + 2 * tg;
        *(float2*)(Og + (size_t)row0 * DD + c) =
            make_float2(o[nt][0] * i0, o[nt][1] * i0);
        *(float2*)(Og + (size_t)(row0 + 8) * DD + c) =
            make_float2(o[nt][2] * i1, o[nt][3] * i1);
    }
}

// ---------------------------------------------------------------------------
extern "C" void kernel_launch(void* const* d_in, const int* in_sizes, int n_in,
                              void* d_out, int out_size)
{
    const float* x   = (const float*)d_in[0];
    const int*   pos = (const int*)  d_in[1];
    const float* Wq  = (const float*)d_in[2];
    const float* Wk  = (const float*)d_in[3];
    const float* Wv  = (const float*)d_in[4];
    const float* Wo  = (const float*)d_in[5];
    float* out = (float*)d_out;

    float *Q, *K, *V, *Aw;
    cudaGetSymbolAddress((void**)&Q,  g_Q);
    cudaGetSymbolAddress((void**)&K,  g_K);
    cudaGetSymbolAddress((void**)&V,  g_V);
    cudaGetSymbolAddress((void**)&Aw, g_A);

    cudaFuncSetAttribute(flash_mma, cudaFuncAttributeMaxDynamicSharedMemorySize,
                         F_SMEM);

    dim3 gg(DD / 128, BS_ROWS / 128);   // (8, 64)

    gemm_tf32<<<gg, 256>>>(x, Wq, Q, BS_ROWS, DD, DD);
    gemm_tf32<<<gg, 256>>>(x, Wk, K, BS_ROWS, DD, DD);
    gemm_tf32<<<gg, 256>>>(x, Wv, V, BS_ROWS, DD, DD);

    const int rope_elems = BS_ROWS * 512;
    rope_kernel<<<rope_elems / 256, 256>>>(Q, pos);
    rope_kernel<<<rope_elems / 256, 256>>>(K, pos);

    flash_mma<<<dim3(SS / 64, HH, BB), 128, F_SMEM>>>(Q, K, V, Aw);

    gemm_tf32<<<gg, 256>>>(Aw, Wo, out, BS_ROWS, DD, DD);
}